// round 16
// baseline (speedup 1.0000x reference)
#include <cuda_runtime.h>
#include <cuda_fp16.h>
#include <cstdint>

// Causal muP attention (scale=1/dhead), B=2 H=16 L=2048 D=64, fp32 in/out.
// R16 = R14/R15 datapath (prepass fp16 fragment tiles + cp.async pipeline,
//   BN=64, zero-C GEMM1, ones-column row sums) restructured to 256 threads:
//   8 warps x 16 q-rows => regs ~105 (no staging regs thanks to cp.async)
//   => 2 CTA/SM = 16 warps/SM = 4 warps/SMSP to hide the GEMM->MUFU chain.

#define BM 128
#define BN 64
#define DD 64
#define NTHREADS 256
#define NSTAGES 4

#define TILE_U32 2048                    // 8KB per converted tile
#define NTILES   32                      // L / BN
#define NBH      32                      // B*H

__device__ uint4 g_Kh4[NBH * NTILES * (TILE_U32 / 4)];
__device__ uint4 g_Vh4[NBH * NTILES * (TILE_U32 / 4)];

#define SMEM_U32 (2 * NSTAGES * TILE_U32)
#define SMEM_BYTES (SMEM_U32 * 4)        // 65536

__device__ __forceinline__ float ex2(float x) {
    float y;
    asm("ex2.approx.f32 %0, %1;" : "=f"(y) : "f"(x));
    return y;
}
__device__ __forceinline__ uint32_t packh2(float lo, float hi) {
    uint32_t r;
    asm("cvt.rn.f16x2.f32 %0, %1, %2;" : "=r"(r) : "f"(hi), "f"(lo));
    return r;
}
__device__ __forceinline__ void mma_f16(float* d,
                                        uint32_t a0, uint32_t a1, uint32_t a2, uint32_t a3,
                                        uint32_t b0, uint32_t b1) {
    asm volatile(
        "mma.sync.aligned.m16n8k16.row.col.f32.f16.f16.f32 "
        "{%0,%1,%2,%3}, {%4,%5,%6,%7}, {%8,%9}, {%0,%1,%2,%3};"
        : "+f"(d[0]), "+f"(d[1]), "+f"(d[2]), "+f"(d[3])
        : "r"(a0), "r"(a1), "r"(a2), "r"(a3), "r"(b0), "r"(b1));
}
__device__ __forceinline__ void mma_f16_zc(float* d,
                                           uint32_t a0, uint32_t a1, uint32_t a2, uint32_t a3,
                                           uint32_t b0, uint32_t b1, float z) {
    asm volatile(
        "mma.sync.aligned.m16n8k16.row.col.f32.f16.f16.f32 "
        "{%0,%1,%2,%3}, {%4,%5,%6,%7}, {%8,%9}, {%10,%10,%10,%10};"
        : "=f"(d[0]), "=f"(d[1]), "=f"(d[2]), "=f"(d[3])
        : "r"(a0), "r"(a1), "r"(a2), "r"(a3), "r"(b0), "r"(b1), "f"(z));
}
__device__ __forceinline__ uint32_t smem_u32(const void* p) {
    uint32_t a;
    asm("{ .reg .u64 t; cvta.to.shared.u64 t, %1; cvt.u32.u64 %0, t; }"
        : "=r"(a) : "l"(p));
    return a;
}
__device__ __forceinline__ void cpa16(uint32_t saddr, const void* g) {
    asm volatile("cp.async.cg.shared.global [%0], [%1], 16;"
                 :: "r"(saddr), "l"(g) : "memory");
}
#define CP_COMMIT() asm volatile("cp.async.commit_group;" ::: "memory")
#define CP_WAIT()   asm volatile("cp.async.wait_group %0;" :: "n"(NSTAGES - 2) : "memory")

// ---- prepass helpers (128-thread layout, unchanged from R14) ----
__device__ __forceinline__ void scatter_k(uint32_t* Kc, const float4* kr, int tid) {
    const int d4   = (tid & 15) * 4;
    const int ks   = d4 >> 4;
    const int rem  = d4 & 15;
    const int ca   = (rem & 7) >> 1;
    const int breg = rem >> 3;
    const int n    = tid >> 4;
    #pragma unroll
    for (int t = 0; t < 8; t++) {
        const int npair  = t >> 1;
        const int parity = t & 1;
        const int sw     = ks ^ npair;
        const int base   = (ks * 4 + npair) * 32;
        uint32_t h2a = packh2(kr[t].x, kr[t].y);
        uint32_t h2b = packh2(kr[t].z, kr[t].w);
        Kc[(base + ((n * 4 + ca)     ^ sw)) * 4 + parity * 2 + breg] = h2a;
        Kc[(base + ((n * 4 + ca + 1) ^ sw)) * 4 + parity * 2 + breg] = h2b;
    }
}
__device__ __forceinline__ void scatter_v(uint32_t* Vc, const float4* vlo,
                                          const float4* vhi, int tid) {
    const int d4   = (tid & 15) * 4;
    const int g    = tid >> 4;
    const int ckv  = g & 3;
    const int breg = g >> 2;
    #pragma unroll
    for (int t = 0; t < 4; t++) {
        const float lo[4] = {vlo[t].x, vlo[t].y, vlo[t].z, vlo[t].w};
        const float hi[4] = {vhi[t].x, vhi[t].y, vhi[t].z, vhi[t].w};
        #pragma unroll
        for (int e = 0; e < 4; e++) {
            const int d      = d4 + e;
            const int npair  = d >> 4;
            const int parity = (d >> 3) & 1;
            const int nd     = d & 7;
            const int sw     = t ^ npair;
            Vc[((t * 4 + npair) * 32 + ((nd * 4 + ckv) ^ sw)) * 4 + parity * 2 + breg]
                = packh2(lo[e], hi[e]);
        }
    }
}

__global__ __launch_bounds__(128)
void convert_kv_kernel(const float* __restrict__ K, const float* __restrict__ V)
{
    __shared__ uint32_t sK[TILE_U32];
    __shared__ uint32_t sV[TILE_U32];
    const int jt  = blockIdx.x;
    const int bh  = blockIdx.y;
    const int tid = threadIdx.x;
    const float* Kg = K + ((size_t)bh * 2048 + jt * BN) * DD;
    const float* Vg = V + ((size_t)bh * 2048 + jt * BN) * DD;

    float4 kr[8];
    #pragma unroll
    for (int t = 0; t < 8; t++)
        kr[t] = *(const float4*)(Kg + (size_t)((tid >> 4) + t * 8) * DD + (tid & 15) * 4);
    scatter_k(sK, kr, tid);

    float4 vlo[4], vhi[4];
    #pragma unroll
    for (int t = 0; t < 4; t++) {
        int kv0 = 2 * (tid >> 4) + 16 * t;
        vlo[t] = *(const float4*)(Vg + (size_t)kv0 * DD + (tid & 15) * 4);
        vhi[t] = *(const float4*)(Vg + (size_t)(kv0 + 1) * DD + (tid & 15) * 4);
    }
    scatter_v(sV, vlo, vhi, tid);
    __syncthreads();

    uint4* outK = g_Kh4 + ((size_t)bh * NTILES + jt) * (TILE_U32 / 4);
    uint4* outV = g_Vh4 + ((size_t)bh * NTILES + jt) * (TILE_U32 / 4);
    #pragma unroll
    for (int c = 0; c < 4; c++) {
        outK[tid + c * 128] = ((const uint4*)sK)[tid + c * 128];
        outV[tid + c * 128] = ((const uint4*)sV)[tid + c * 128];
    }
}

// ---- main kernel: 256 threads, 8 warps x 16 q-rows ----
__global__ __launch_bounds__(NTHREADS, 2)
void fa_fp16_kernel(const float* __restrict__ Q, float* __restrict__ O, int L)
{
    extern __shared__ uint32_t smu[];
    uint32_t* smK = smu;                     // [NSTAGES][TILE_U32]
    uint32_t* smV = smu + NSTAGES * TILE_U32;
    const uint32_t smK_a = smem_u32(smK);
    const uint32_t smV_a = smem_u32(smV);

    const int qi    = (gridDim.x - 1) - blockIdx.x;   // heavy tiles first
    const int bh    = blockIdx.y;
    const int qbase = qi * BM;
    const float qscale = 1.4426950408889634f / 64.0f; // log2(e)/dhead

    const int tid  = threadIdx.x;
    const int w    = tid >> 5;      // warp 0..7, owns rows [w*16, w*16+16)
    const int lane = tid & 31;

    const float* Qg = Q + (size_t)bh * L * DD;
    float*       Og = O + (size_t)bh * L * DD;
    const uint4* Ksrc = g_Kh4 + (size_t)bh * NTILES * (TILE_U32 / 4);
    const uint4* Vsrc = g_Vh4 + (size_t)bh * NTILES * (TILE_U32 / 4);

    const int njt = 2 * qi + 2;

    // ---- prologue: issue first NSTAGES-1 tiles (2 K + 2 V uint4s/thread) ----
    #pragma unroll
    for (int i = 0; i < NSTAGES - 1; i++) {
        if (i < njt) {
            const uint4* gk = Ksrc + i * (TILE_U32 / 4) + tid;
            const uint4* gv = Vsrc + i * (TILE_U32 / 4) + tid;
            uint32_t dk = smK_a + (i * TILE_U32 + tid * 4) * 4;
            uint32_t dv = smV_a + (i * TILE_U32 + tid * 4) * 4;
            #pragma unroll
            for (int c = 0; c < 2; c++) {
                cpa16(dk + c * 4096, gk + c * 256);
                cpa16(dv + c * 4096, gv + c * 256);
            }
        }
        CP_COMMIT();
    }

    // ---- Q A-fragments in registers (fp16, scale folded, loaded once) ----
    uint32_t q[4][4];
    {
        const int r0 = qbase + w * 16 + (lane >> 2);
        const int cb = 2 * (lane & 3);
        const float* qa = Qg + (size_t)r0 * DD;
        const float* qb = qa + 8 * DD;
        #pragma unroll
        for (int ks = 0; ks < 4; ks++) {
            const int c0 = ks * 16 + cb;
            float2 va  = *(const float2*)(qa + c0);
            float2 vb  = *(const float2*)(qb + c0);
            float2 va8 = *(const float2*)(qa + c0 + 8);
            float2 vb8 = *(const float2*)(qb + c0 + 8);
            q[ks][0] = packh2(va.x  * qscale, va.y  * qscale);
            q[ks][1] = packh2(vb.x  * qscale, vb.y  * qscale);
            q[ks][2] = packh2(va8.x * qscale, va8.y * qscale);
            q[ks][3] = packh2(vb8.x * qscale, vb8.y * qscale);
        }
    }

    float s[8][4], o[8][4];
    float lf[4];                          // ones-column row-sum fragments
    #pragma unroll
    for (int j = 0; j < 4; j++) lf[j] = 0.0f;
    #pragma unroll
    for (int dt = 0; dt < 8; dt++)
        #pragma unroll
        for (int j = 0; j < 4; j++) o[dt][j] = 0.0f;

    const uint32_t ones = ((lane >> 2) == 0) ? 0x3C003C00u : 0u;
    const float    fz   = 0.0f;
    const int      wrow0 = qbase + w * 16;

    for (int jt = 0; jt < njt; jt++) {
        const int  st     = jt & (NSTAGES - 1);
        const int  kbase  = jt * BN;
        const bool active = (kbase <= wrow0 + 15);

        CP_WAIT();
        __syncthreads();

        // issue tile jt+NSTAGES-1
        {
            const int nx = jt + NSTAGES - 1;
            if (nx < njt) {
                const int nst = nx & (NSTAGES - 1);
                const uint4* gk = Ksrc + nx * (TILE_U32 / 4) + tid;
                const uint4* gv = Vsrc + nx * (TILE_U32 / 4) + tid;
                uint32_t dk = smK_a + (nst * TILE_U32 + tid * 4) * 4;
                uint32_t dv = smV_a + (nst * TILE_U32 + tid * 4) * 4;
                #pragma unroll
                for (int c = 0; c < 2; c++) {
                    cpa16(dk + c * 4096, gk + c * 256);
                    cpa16(dv + c * 4096, gv + c * 256);
                }
            }
            CP_COMMIT();
        }

        if (!active) continue;

        const uint32_t* Kc = smK + st * TILE_U32;
        const uint32_t* Vc = smV + st * TILE_U32;

        // ---- GEMM1: S = Q K^T (ks=0 zero-C write) ----
        #pragma unroll
        for (int np = 0; np < 4; np++) {
            const uint4 b = *(const uint4*)&Kc[((0 * 4 + np) * 32 + (lane ^ np)) * 4];
            mma_f16_zc(s[2*np],   q[0][0], q[0][1], q[0][2], q[0][3], b.x, b.y, fz);
            mma_f16_zc(s[2*np+1], q[0][0], q[0][1], q[0][2], q[0][3], b.z, b.w, fz);
        }
        #pragma unroll
        for (int ks = 1; ks < 4; ks++) {
            #pragma unroll
            for (int np = 0; np < 4; np++) {
                const uint4 b = *(const uint4*)
                    &Kc[((ks * 4 + np) * 32 + (lane ^ (ks ^ np))) * 4];
                mma_f16(s[2*np],   q[ks][0], q[ks][1], q[ks][2], q[ks][3], b.x, b.y);
                mma_f16(s[2*np+1], q[ks][0], q[ks][1], q[ks][2], q[ks][3], b.z, b.w);
            }
        }

        // ---- causal mask ----
        if (kbase + BN - 1 > wrow0) {
            int rA = wrow0 + (lane >> 2);
            int rB = rA + 8;
            #pragma unroll
            for (int nt = 0; nt < 8; nt++) {
                int col = kbase + nt * 8 + 2 * (lane & 3);
                if (col     > rA) s[nt][0] = -1e30f;
                if (col + 1 > rA) s[nt][1] = -1e30f;
                if (col     > rB) s[nt][2] = -1e30f;
                if (col + 1 > rB) s[nt][3] = -1e30f;
            }
        }
        // ---- softmax numerator P = 2^s (fixed max 0, muP) ----
        #pragma unroll
        for (int nt = 0; nt < 8; nt++) {
            s[nt][0] = ex2(s[nt][0]);
            s[nt][1] = ex2(s[nt][1]);
            s[nt][2] = ex2(s[nt][2]);
            s[nt][3] = ex2(s[nt][3]);
        }
        // ---- GEMM2: O += P V; l += P . 1 ----
        #pragma unroll
        for (int ks2 = 0; ks2 < 4; ks2++) {
            uint32_t pa[4];
            pa[0] = packh2(s[2*ks2][0],   s[2*ks2][1]);
            pa[1] = packh2(s[2*ks2][2],   s[2*ks2][3]);
            pa[2] = packh2(s[2*ks2+1][0], s[2*ks2+1][1]);
            pa[3] = packh2(s[2*ks2+1][2], s[2*ks2+1][3]);
            #pragma unroll
            for (int np = 0; np < 4; np++) {
                const uint4 b = *(const uint4*)
                    &Vc[((ks2 * 4 + np) * 32 + (lane ^ (ks2 ^ np))) * 4];
                mma_f16(o[2*np],   pa[0], pa[1], pa[2], pa[3], b.x, b.y);
                mma_f16(o[2*np+1], pa[0], pa[1], pa[2], pa[3], b.z, b.w);
            }
            mma_f16(lf, pa[0], pa[1], pa[2], pa[3], ones, ones);
        }
    }

    // ---- epilogue: l in quad-leader's lf c0 (row rA) / c2 (row rB) ----
    {
        const int leader = lane & ~3;
        float lA = __shfl_sync(0xffffffffu, lf[0], leader);
        float lB = __shfl_sync(0xffffffffu, lf[2], leader);
        float invA = 1.0f / lA;
        float invB = 1.0f / lB;

        int rA = qbase + w * 16 + (lane >> 2);
        int rB = rA + 8;
        #pragma unroll
        for (int dt = 0; dt < 8; dt++) {
            int d0 = dt * 8 + 2 * (lane & 3);
            float2 oa = make_float2(o[dt][0] * invA, o[dt][1] * invA);
            float2 ob = make_float2(o[dt][2] * invB, o[dt][3] * invB);
            *(float2*)(Og + (size_t)rA * DD + d0) = oa;
            *(float2*)(Og + (size_t)rB * DD + d0) = ob;
        }
    }
}

extern "C" void kernel_launch(void* const* d_in, const int* in_sizes, int n_in,
                              void* d_out, int out_size)
{
    const float* Q = (const float*)d_in[0];
    const float* K = (const float*)d_in[1];
    const float* V = (const float*)d_in[2];
    float* O = (float*)d_out;

    const int L = 2048;

    dim3 cgrid(NTILES, NBH);
    convert_kv_kernel<<<cgrid, 128>>>(K, V);

    cudaFuncSetAttribute(fa_fp16_kernel,
                         cudaFuncAttributeMaxDynamicSharedMemorySize, SMEM_BYTES);
    dim3 grid(L / BM, NBH);   // (16, 32)
    fa_fp16_kernel<<<grid, NTHREADS, SMEM_BYTES>>>(Q, O, L);
}